// round 16
// baseline (speedup 1.0000x reference)
#include <cuda_runtime.h>
#include <cuda_fp16.h>
#include <cstdint>

#define HT    256
#define WD    512
#define HWSZ  (HT*WD)          // 131072
#define CIN   64
#define COUT  64
#define KK2   9
#define KP    64               // K' = 64 (plain fp16 GEMM)
#define ROWB  128              // bytes per A row (KP * 2)

// ---------------- device scratch --------------------------------------------
__device__ __align__(16) uint16_t g_x16[2u * HT * WD * CIN];   // x in NHWC fp16
// B in mma-fragment order: [tap][kc][np][lane] = uint4 {r0,r1,r2,r3}
__device__ __align__(16) uint4 g_wf[KK2 * 4 * 4 * 32];         // 73728 B
__device__ int4  g_off[KK2 * HWSZ];            // corner byte-offsets (fp16 NHWC)
__device__ uint4 g_wq[KK2 * HWSZ];             // bilinear weights, replicated f16x2

// ---------------- smem layout (bytes) ---------------------------------------
#define OFF_A   0
#define A_BYTES (128 * ROWB)          // 16384
#define OFF_PO  A_BYTES               // 16384
#define OFF_PW  (OFF_PO + 2048)       // 18432
#define SMEM_SZ (OFF_PW + 2048)       // 20480

// 16B-chunk swizzle within a 128B row (8 chunks)
__device__ __forceinline__ uint32_t swzc(uint32_t c, uint32_t r) {
    return (c & ~7u) | ((c ^ r) & 7u);
}
__device__ __forceinline__ uint16_t f2h(float f) {
    uint16_t r; asm("cvt.rn.f16.f32 %0, %1;" : "=h"(r) : "f"(f)); return r;
}
__device__ __forceinline__ uint32_t f2h2(float lo, float hi) {
    uint32_t r;
    asm("cvt.rn.f16x2.f32 %0, %1, %2;" : "=r"(r) : "f"(hi), "f"(lo));
    return r;
}
__device__ __forceinline__ uint32_t hmul2(uint32_t a, uint32_t b) {
    uint32_t r; asm("mul.f16x2 %0, %1, %2;" : "=r"(r) : "r"(a), "r"(b)); return r;
}
__device__ __forceinline__ uint32_t hfma2(uint32_t a, uint32_t b, uint32_t c) {
    uint32_t r; asm("fma.rn.f16x2 %0, %1, %2, %3;" : "=r"(r) : "r"(a), "r"(b), "r"(c));
    return r;
}
__device__ __forceinline__ uint32_t smem_u32(const void* p) {
    uint32_t a;
    asm("{ .reg .u64 t; cvta.to.shared.u64 t, %1; cvt.u32.u64 %0, t; }" : "=r"(a) : "l"(p));
    return a;
}
__device__ __forceinline__ void ldsm4(uint32_t r[4], uint32_t addr) {
    asm volatile("ldmatrix.sync.aligned.m8n8.x4.shared.b16 {%0,%1,%2,%3}, [%4];"
                 : "=r"(r[0]), "=r"(r[1]), "=r"(r[2]), "=r"(r[3]) : "r"(addr));
}
__device__ __forceinline__ void mma_f16(float c[4], const uint32_t a[4],
                                        uint32_t b0, uint32_t b1) {
    asm volatile("mma.sync.aligned.m16n8k16.row.col.f32.f16.f16.f32 "
                 "{%0,%1,%2,%3}, {%4,%5,%6,%7}, {%8,%9}, {%0,%1,%2,%3};"
                 : "+f"(c[0]), "+f"(c[1]), "+f"(c[2]), "+f"(c[3])
                 : "r"(a[0]), "r"(a[1]), "r"(a[2]), "r"(a[3]), "r"(b0), "r"(b1));
}

// ---------------- prep: NCHW fp32 -> NHWC fp16 -------------------------------
__global__ void transpose_x(const float* __restrict__ x) {
    __shared__ float tile[32][33];
    const int w0 = blockIdx.x * 32, c0 = blockIdx.y * 32, nh = blockIdx.z;
    const int n = nh >> 8, h = nh & (HT - 1);
    const float* src = x + ((size_t)(n * CIN + c0)) * HWSZ + h * WD + w0;
#pragma unroll
    for (int i = 0; i < 32; i += 8)
        tile[threadIdx.y + i][threadIdx.x] = src[(size_t)(threadIdx.y + i) * HWSZ + threadIdx.x];
    __syncthreads();
    uint16_t* dst = g_x16 + ((size_t)nh * WD + w0) * CIN + c0;
#pragma unroll
    for (int i = 0; i < 32; i += 8)
        dst[(size_t)(threadIdx.y + i) * CIN + threadIdx.x] =
            f2h(tile[threadIdx.x][threadIdx.y + i]);
}

// ---------------- prep: weights -> mma B-fragment order ----------------------
// For (tap, kc, np, lane): n0 = 16np + lane/4, k0 = 16kc + 2(lane%4)
//   r0 = {B[n0][k0],   B[n0][k0+1]}     r1 = {B[n0][k0+8],   B[n0][k0+9]}
//   r2 = {B[n0+8][k0], B[n0+8][k0+1]}   r3 = {B[n0+8][k0+8], B[n0+8][k0+9]}
// where B[n][k] = fp16(wgt[n][c=k][tap]).
__global__ void weight_frag(const float* __restrict__ wgt) {
    int idx = blockIdx.x * 256 + threadIdx.x;   // 0 .. 9*4*4*32-1
    if (idx >= KK2 * 4 * 4 * 32) return;
    int lane = idx & 31, np = (idx >> 5) & 3, kc = (idx >> 7) & 3, tap = idx >> 9;
    int n0 = np * 16 + (lane >> 2);
    int k0 = kc * 16 + 2 * (lane & 3);
    auto B = [&](int n, int k) -> float {
        return wgt[((size_t)n * CIN + k) * KK2 + tap];
    };
    uint4 v;
    v.x = (uint32_t)f2h(B(n0,     k0))     | ((uint32_t)f2h(B(n0,     k0 + 1)) << 16);
    v.y = (uint32_t)f2h(B(n0,     k0 + 8)) | ((uint32_t)f2h(B(n0,     k0 + 9)) << 16);
    v.z = (uint32_t)f2h(B(n0 + 8, k0))     | ((uint32_t)f2h(B(n0 + 8, k0 + 1)) << 16);
    v.w = (uint32_t)f2h(B(n0 + 8, k0 + 8)) | ((uint32_t)f2h(B(n0 + 8, k0 + 9)) << 16);
    g_wf[idx] = v;
}

// ---------------- prep: bilinear offsets + f16x2 weights --------------------
__global__ void precomp(const float* __restrict__ pos) {
    int hw = blockIdx.x * 256 + threadIdx.x;
#pragma unroll 1
    for (int tap = 0; tap < KK2; tap++) {
        const float py = pos[(size_t)(2 * tap) * HWSZ + hw];
        const float px = pos[(size_t)(2 * tap + 1) * HWSZ + hw];
        const float y0f = floorf(py), x0f = floorf(px);
        const float dy = py - y0f, dx = px - x0f;
        const float y1f = y0f + 1.0f, x1f = x0f + 1.0f;
        const float vy0 = (y0f >= 0.0f && y0f <= (float)(HT - 1)) ? 1.0f : 0.0f;
        const float vy1 = (y1f >= 0.0f && y1f <= (float)(HT - 1)) ? 1.0f : 0.0f;
        const float vx0 = (x0f >= 0.0f && x0f <= (float)(WD - 1)) ? 1.0f : 0.0f;
        const float vx1 = (x1f >= 0.0f && x1f <= (float)(WD - 1)) ? 1.0f : 0.0f;
        const float q00 = (1.0f - dy) * (1.0f - dx) * vy0 * vx0;
        const float q01 = (1.0f - dy) * dx          * vy0 * vx1;
        const float q10 = dy * (1.0f - dx)          * vy1 * vx0;
        const float q11 = dy * dx                   * vy1 * vx1;
        const int yi0 = min(max((int)y0f, 0), HT - 1);
        const int yi1 = min(max((int)y1f, 0), HT - 1);
        const int xi0 = min(max((int)x0f, 0), WD - 1);
        const int xi1 = min(max((int)x1f, 0), WD - 1);
        int4 off;   // byte offsets into fp16 NHWC (128 B per pixel record)
        off.x = (yi0 * WD + xi0) * 128;
        off.y = (yi0 * WD + xi1) * 128;
        off.z = (yi1 * WD + xi0) * 128;
        off.w = (yi1 * WD + xi1) * 128;
        uint4 qq;   // each bilinear weight replicated into both fp16 halves
        qq.x = f2h2(q00, q00); qq.y = f2h2(q01, q01);
        qq.z = f2h2(q10, q10); qq.w = f2h2(q11, q11);
        g_off[tap * HWSZ + hw] = off;
        g_wq[tap * HWSZ + hw]  = qq;
    }
}

// ---------------- main: fp16 gather (HFMA2) + mma, B from GMEM fragments ----
// block = 128 threads (4 warps), tile = 128 pixels x 64 couts, grid 2048
// warp w: gathers + owns pixels [w*32, w*32+32); mma M=32, N=64, K'=64
// NO block-wide barriers. __launch_bounds__(128,5): cap 102 regs -> 20 warps/SM
__global__ __launch_bounds__(128, 5)
void sphere_mma(float* __restrict__ out) {
    extern __shared__ char smem[];
    const uint32_t sb = smem_u32(smem);
    const int t = threadIdx.x, w = t >> 5, lane = t & 31;

    const int pixbase = blockIdx.x << 7;         // 128 pixels per block
    const int n   = pixbase >> 17;
    const int hwb = pixbase & (HWSZ - 1);
    const char* __restrict__ xb = (const char*)(g_x16 + (size_t)n * (HWSZ * CIN));

    int4*  Po = (int4*)(smem + OFF_PO);
    uint4* Pw = (uint4*)(smem + OFF_PW);
    const uint4* __restrict__ bf = g_wf + lane;  // + tap*512 + kc*128 + np*32

    float acc[2][8][4];
#pragma unroll
    for (int mt = 0; mt < 2; mt++)
#pragma unroll
        for (int nt = 0; nt < 8; nt++)
#pragma unroll
            for (int j = 0; j < 4; j++) acc[mt][nt][j] = 0.0f;

    const uint32_t lb = lane * 4;                // byte offset of channels (2l,2l+1)
    const uint32_t intra = (lane & 3) * 4;

#pragma unroll 1
    for (int tap = 0; tap < KK2; tap++) {
        // ---- stage this warp's Po/Pw (warp-private region) ----
        Po[w * 32 + lane] = g_off[tap * HWSZ + hwb + w * 32 + lane];
        Pw[w * 32 + lane] = g_wq[tap * HWSZ + hwb + w * 32 + lane];
        __syncwarp();

        // ---- gather own 32 pixels: 4 corner u32 loads, HFMA2 blend, 1 STS ----
#pragma unroll 2
        for (int g = 0; g < 8; g++) {
            const int p0 = w * 32 + g * 4;
            int4  o[4];
            uint4 q[4];
#pragma unroll
            for (int j = 0; j < 4; j++) { o[j] = Po[p0 + j]; q[j] = Pw[p0 + j]; }

            uint32_t C[4][4];
#pragma unroll
            for (int j = 0; j < 4; j++) {
                C[j][0] = *(const uint32_t*)(xb + o[j].x + lb);
                C[j][1] = *(const uint32_t*)(xb + o[j].y + lb);
                C[j][2] = *(const uint32_t*)(xb + o[j].z + lb);
                C[j][3] = *(const uint32_t*)(xb + o[j].w + lb);
            }
#pragma unroll
            for (int j = 0; j < 4; j++) {
                const uint32_t pl = (uint32_t)(p0 + j);
                uint32_t sres = hmul2(q[j].x, C[j][0]);
                sres = hfma2(q[j].y, C[j][1], sres);
                sres = hfma2(q[j].z, C[j][2], sres);
                sres = hfma2(q[j].w, C[j][3], sres);
                // channels (2l, 2l+1) -> row bytes [4l, 4l+4) -> chunk l>>2
                *(uint32_t*)(smem + pl * ROWB +
                             swzc(lane >> 2, pl) * 16 + intra) = sres;
            }
        }
        __syncwarp();

        // ---- mma: M=32 (own rows), N=64, K'=64; one B uint4 live at a time ----
        const uint32_t abase = sb + OFF_A;
        const uint4* __restrict__ bft = bf + tap * 512;
#pragma unroll
        for (int kc = 0; kc < 4; kc++) {
            uint32_t a[2][4];
#pragma unroll
            for (int mt = 0; mt < 2; mt++) {
                uint32_t row = (uint32_t)(w * 32 + mt * 16 + (lane & 15));
                uint32_t kch = (uint32_t)(kc * 2 + (lane >> 4));
                ldsm4(a[mt], abase + row * ROWB + swzc(kch, row) * 16);
            }
#pragma unroll
            for (int np = 0; np < 4; np++) {
                uint4 v = bft[kc * 128 + np * 32];
                mma_f16(acc[0][2 * np],     a[0], v.x, v.y);
                mma_f16(acc[0][2 * np + 1], a[0], v.z, v.w);
                mma_f16(acc[1][2 * np],     a[1], v.x, v.y);
                mma_f16(acc[1][2 * np + 1], a[1], v.z, v.w);
            }
        }
        __syncwarp();   // fence: A/PoPw WAR before next tap's overwrite
    }

    // ---- epilogue ----------------------------------------------------------
    float* ob = out + (size_t)n * COUT * HWSZ + hwb;
#pragma unroll
    for (int mt = 0; mt < 2; mt++) {
        const int pl = w * 32 + mt * 16 + (lane >> 2);
#pragma unroll
        for (int nt = 0; nt < 8; nt++) {
            const int co = nt * 8 + (lane & 3) * 2;
            ob[(size_t)co * HWSZ + pl]           = acc[mt][nt][0];
            ob[(size_t)(co + 1) * HWSZ + pl]     = acc[mt][nt][1];
            ob[(size_t)co * HWSZ + pl + 8]       = acc[mt][nt][2];
            ob[(size_t)(co + 1) * HWSZ + pl + 8] = acc[mt][nt][3];
        }
    }
}

// ---------------- launch ----------------------------------------------------
extern "C" void kernel_launch(void* const* d_in, const int* in_sizes, int n_in,
                              void* d_out, int out_size) {
    const float* x   = (const float*)d_in[0];
    const float* wgt = (const float*)d_in[1];
    const float* pos = (const float*)d_in[2];
    float* out = (float*)d_out;

    transpose_x<<<dim3(WD / 32, CIN / 32, 2 * HT), dim3(32, 8)>>>(x);
    weight_frag<<<(KK2 * 4 * 4 * 32 + 255) / 256, 256>>>(wgt);
    precomp<<<HWSZ / 256, 256>>>(pos);

    cudaFuncSetAttribute(sphere_mma, cudaFuncAttributeMaxDynamicSharedMemorySize, SMEM_SZ);
    sphere_mma<<<(2 * HWSZ) / 128, 128, SMEM_SZ>>>(out);
}

// round 17
// speedup vs baseline: 1.2100x; 1.2100x over previous
#include <cuda_runtime.h>
#include <cuda_fp16.h>
#include <cstdint>

#define HT    256
#define WD    512
#define HWSZ  (HT*WD)          // 131072
#define CIN   64
#define COUT  64
#define KK2   9
#define KP    64               // K' = 64 (plain fp16 GEMM)
#define ROWB  128              // bytes per A row (KP * 2)

// ---------------- device scratch --------------------------------------------
__device__ __align__(16) uint16_t g_x16[2u * HT * WD * CIN];   // x in NHWC fp16
// B in mma-fragment order: [tap][kc][np][lane] = uint4 {r0,r1,r2,r3}
__device__ __align__(16) uint4 g_wf[KK2 * 4 * 4 * 32];         // 73728 B
__device__ int4  g_off[KK2 * HWSZ];            // corner byte-offsets (fp16 NHWC)
__device__ uint4 g_wq[KK2 * HWSZ];             // bilinear weights, replicated f16x2

// ---------------- smem layout (bytes) ---------------------------------------
#define OFF_A   0
#define A_BYTES (128 * ROWB)          // 16384
#define OFF_PO  A_BYTES               // 16384
#define OFF_PW  (OFF_PO + 2048)       // 18432
#define SMEM_SZ (OFF_PW + 2048)       // 20480

// 16B-chunk swizzle within a 128B row (8 chunks)
__device__ __forceinline__ uint32_t swzc(uint32_t c, uint32_t r) {
    return (c & ~7u) | ((c ^ r) & 7u);
}
__device__ __forceinline__ uint16_t f2h(float f) {
    uint16_t r; asm("cvt.rn.f16.f32 %0, %1;" : "=h"(r) : "f"(f)); return r;
}
__device__ __forceinline__ uint32_t f2h2(float lo, float hi) {
    uint32_t r;
    asm("cvt.rn.f16x2.f32 %0, %1, %2;" : "=r"(r) : "f"(hi), "f"(lo));
    return r;
}
__device__ __forceinline__ uint32_t hmul2(uint32_t a, uint32_t b) {
    uint32_t r; asm("mul.f16x2 %0, %1, %2;" : "=r"(r) : "r"(a), "r"(b)); return r;
}
__device__ __forceinline__ uint32_t hfma2(uint32_t a, uint32_t b, uint32_t c) {
    uint32_t r; asm("fma.rn.f16x2 %0, %1, %2, %3;" : "=r"(r) : "r"(a), "r"(b), "r"(c));
    return r;
}
__device__ __forceinline__ uint32_t smem_u32(const void* p) {
    uint32_t a;
    asm("{ .reg .u64 t; cvta.to.shared.u64 t, %1; cvt.u32.u64 %0, t; }" : "=r"(a) : "l"(p));
    return a;
}
__device__ __forceinline__ void ldsm4(uint32_t r[4], uint32_t addr) {
    asm volatile("ldmatrix.sync.aligned.m8n8.x4.shared.b16 {%0,%1,%2,%3}, [%4];"
                 : "=r"(r[0]), "=r"(r[1]), "=r"(r[2]), "=r"(r[3]) : "r"(addr));
}
__device__ __forceinline__ void mma_f16(float c[4], const uint32_t a[4],
                                        const uint32_t b[2]) {
    asm volatile("mma.sync.aligned.m16n8k16.row.col.f32.f16.f16.f32 "
                 "{%0,%1,%2,%3}, {%4,%5,%6,%7}, {%8,%9}, {%0,%1,%2,%3};"
                 : "+f"(c[0]), "+f"(c[1]), "+f"(c[2]), "+f"(c[3])
                 : "r"(a[0]), "r"(a[1]), "r"(a[2]), "r"(a[3]), "r"(b[0]), "r"(b[1]));
}

// ---------------- prep: NCHW fp32 -> NHWC fp16, full-width stores ------------
// One block: 32 w-positions x ALL 64 channels. Write phase packs 2 channels
// per thread (fp16x2) -> each warp stores 128B contiguous per w-row.
__global__ void transpose_x(const float* __restrict__ x) {
    __shared__ float tile[64][33];
    const int w0 = blockIdx.x * 32;               // 16 blocks
    const int nh = blockIdx.y;                    // 512 (n*HT + h)
    const int n = nh >> 8, h = nh & (HT - 1);
    const float* src = x + ((size_t)n * CIN) * HWSZ + h * WD + w0;
#pragma unroll
    for (int i = 0; i < 64; i += 8)               // channel = threadIdx.y + i
        tile[threadIdx.y + i][threadIdx.x] =
            src[(size_t)(threadIdx.y + i) * HWSZ + threadIdx.x];
    __syncthreads();
    uint16_t* dst = g_x16 + ((size_t)nh * WD + w0) * CIN;
#pragma unroll
    for (int i = 0; i < 32; i += 8) {             // w-row = threadIdx.y + i
        const int wv = threadIdx.y + i;
        uint32_t pv = f2h2(tile[2 * threadIdx.x][wv],
                           tile[2 * threadIdx.x + 1][wv]);
        *(uint32_t*)(dst + (size_t)wv * CIN + 2 * threadIdx.x) = pv;
    }
}

// ---------------- prep: weights -> mma B-fragment order ----------------------
// For (tap, kc, np, lane): n0 = 16np + lane/4, k0 = 16kc + 2(lane%4)
//   r0 = {B[n0][k0],   B[n0][k0+1]}     r1 = {B[n0][k0+8],   B[n0][k0+9]}
//   r2 = {B[n0+8][k0], B[n0+8][k0+1]}   r3 = {B[n0+8][k0+8], B[n0+8][k0+9]}
// where B[n][k] = fp16(wgt[n][c=k][tap]).
__global__ void weight_frag(const float* __restrict__ wgt) {
    int idx = blockIdx.x * 256 + threadIdx.x;   // 0 .. 9*4*4*32-1
    if (idx >= KK2 * 4 * 4 * 32) return;
    int lane = idx & 31, np = (idx >> 5) & 3, kc = (idx >> 7) & 3, tap = idx >> 9;
    int n0 = np * 16 + (lane >> 2);
    int k0 = kc * 16 + 2 * (lane & 3);
    auto B = [&](int n, int k) -> float {
        return wgt[((size_t)n * CIN + k) * KK2 + tap];
    };
    uint4 v;
    v.x = (uint32_t)f2h(B(n0,     k0))     | ((uint32_t)f2h(B(n0,     k0 + 1)) << 16);
    v.y = (uint32_t)f2h(B(n0,     k0 + 8)) | ((uint32_t)f2h(B(n0,     k0 + 9)) << 16);
    v.z = (uint32_t)f2h(B(n0 + 8, k0))     | ((uint32_t)f2h(B(n0 + 8, k0 + 1)) << 16);
    v.w = (uint32_t)f2h(B(n0 + 8, k0 + 8)) | ((uint32_t)f2h(B(n0 + 8, k0 + 9)) << 16);
    g_wf[idx] = v;
}

// ---------------- prep: bilinear offsets + f16x2 weights --------------------
__global__ void precomp(const float* __restrict__ pos) {
    int hw = blockIdx.x * 256 + threadIdx.x;
#pragma unroll 1
    for (int tap = 0; tap < KK2; tap++) {
        const float py = pos[(size_t)(2 * tap) * HWSZ + hw];
        const float px = pos[(size_t)(2 * tap + 1) * HWSZ + hw];
        const float y0f = floorf(py), x0f = floorf(px);
        const float dy = py - y0f, dx = px - x0f;
        const float y1f = y0f + 1.0f, x1f = x0f + 1.0f;
        const float vy0 = (y0f >= 0.0f && y0f <= (float)(HT - 1)) ? 1.0f : 0.0f;
        const float vy1 = (y1f >= 0.0f && y1f <= (float)(HT - 1)) ? 1.0f : 0.0f;
        const float vx0 = (x0f >= 0.0f && x0f <= (float)(WD - 1)) ? 1.0f : 0.0f;
        const float vx1 = (x1f >= 0.0f && x1f <= (float)(WD - 1)) ? 1.0f : 0.0f;
        const float q00 = (1.0f - dy) * (1.0f - dx) * vy0 * vx0;
        const float q01 = (1.0f - dy) * dx          * vy0 * vx1;
        const float q10 = dy * (1.0f - dx)          * vy1 * vx0;
        const float q11 = dy * dx                   * vy1 * vx1;
        const int yi0 = min(max((int)y0f, 0), HT - 1);
        const int yi1 = min(max((int)y1f, 0), HT - 1);
        const int xi0 = min(max((int)x0f, 0), WD - 1);
        const int xi1 = min(max((int)x1f, 0), WD - 1);
        int4 off;   // byte offsets into fp16 NHWC (128 B per pixel record)
        off.x = (yi0 * WD + xi0) * 128;
        off.y = (yi0 * WD + xi1) * 128;
        off.z = (yi1 * WD + xi0) * 128;
        off.w = (yi1 * WD + xi1) * 128;
        uint4 qq;   // each bilinear weight replicated into both fp16 halves
        qq.x = f2h2(q00, q00); qq.y = f2h2(q01, q01);
        qq.z = f2h2(q10, q10); qq.w = f2h2(q11, q11);
        g_off[tap * HWSZ + hw] = off;
        g_wq[tap * HWSZ + hw]  = qq;
    }
}

// ---------------- main: fp16 gather (HFMA2) + mma, B from GMEM fragments ----
// block = 128 threads (4 warps), tile = 128 pixels x 64 couts, grid 2048
// warp w: gathers + owns pixels [w*32, w*32+32); mma M=32, N=64, K'=64
// NO block-wide barriers: A and PoPw are warp-private, B read-only from gmem.
// (R13 configuration, verified 155.0us: __launch_bounds__(128,4), regs=128.)
__global__ __launch_bounds__(128, 4)
void sphere_mma(float* __restrict__ out) {
    extern __shared__ char smem[];
    const uint32_t sb = smem_u32(smem);
    const int t = threadIdx.x, w = t >> 5, lane = t & 31;

    const int pixbase = blockIdx.x << 7;         // 128 pixels per block
    const int n   = pixbase >> 17;
    const int hwb = pixbase & (HWSZ - 1);
    const char* __restrict__ xb = (const char*)(g_x16 + (size_t)n * (HWSZ * CIN));

    int4*  Po = (int4*)(smem + OFF_PO);
    uint4* Pw = (uint4*)(smem + OFF_PW);
    const uint4* __restrict__ bf = g_wf + lane;  // + tap*512 + kc*128 + np*32

    float acc[2][8][4];
#pragma unroll
    for (int mt = 0; mt < 2; mt++)
#pragma unroll
        for (int nt = 0; nt < 8; nt++)
#pragma unroll
            for (int j = 0; j < 4; j++) acc[mt][nt][j] = 0.0f;

    const uint32_t lb = lane * 4;                // byte offset of channels (2l,2l+1)
    const uint32_t intra = (lane & 3) * 4;

#pragma unroll 1
    for (int tap = 0; tap < KK2; tap++) {
        // ---- stage this warp's Po/Pw (warp-private region) ----
        Po[w * 32 + lane] = g_off[tap * HWSZ + hwb + w * 32 + lane];
        Pw[w * 32 + lane] = g_wq[tap * HWSZ + hwb + w * 32 + lane];
        __syncwarp();

        // ---- gather own 32 pixels: 4 corner u32 loads, HFMA2 blend, 1 STS ----
#pragma unroll 2
        for (int g = 0; g < 8; g++) {
            const int p0 = w * 32 + g * 4;
            int4  o[4];
            uint4 q[4];
#pragma unroll
            for (int j = 0; j < 4; j++) { o[j] = Po[p0 + j]; q[j] = Pw[p0 + j]; }

            uint32_t C[4][4];
#pragma unroll
            for (int j = 0; j < 4; j++) {
                C[j][0] = *(const uint32_t*)(xb + o[j].x + lb);
                C[j][1] = *(const uint32_t*)(xb + o[j].y + lb);
                C[j][2] = *(const uint32_t*)(xb + o[j].z + lb);
                C[j][3] = *(const uint32_t*)(xb + o[j].w + lb);
            }
#pragma unroll
            for (int j = 0; j < 4; j++) {
                const uint32_t pl = (uint32_t)(p0 + j);
                uint32_t sres = hmul2(q[j].x, C[j][0]);
                sres = hfma2(q[j].y, C[j][1], sres);
                sres = hfma2(q[j].z, C[j][2], sres);
                sres = hfma2(q[j].w, C[j][3], sres);
                // channels (2l, 2l+1) -> row bytes [4l, 4l+4) -> chunk l>>2
                *(uint32_t*)(smem + pl * ROWB +
                             swzc(lane >> 2, pl) * 16 + intra) = sres;
            }
        }
        __syncwarp();

        // ---- mma: M=32 (own rows), N=64, K'=64; B fragments via LDG.128 ----
        const uint32_t abase = sb + OFF_A;
        const uint4* __restrict__ bft = bf + tap * 512;
#pragma unroll
        for (int kc = 0; kc < 4; kc++) {
            uint32_t a[2][4];
#pragma unroll
            for (int mt = 0; mt < 2; mt++) {
                uint32_t row = (uint32_t)(w * 32 + mt * 16 + (lane & 15));
                uint32_t kch = (uint32_t)(kc * 2 + (lane >> 4));
                ldsm4(a[mt], abase + row * ROWB + swzc(kch, row) * 16);
            }
            uint32_t b[8][2];
#pragma unroll
            for (int np = 0; np < 4; np++) {
                uint4 v = bft[kc * 128 + np * 32];
                b[2 * np][0]     = v.x; b[2 * np][1]     = v.y;
                b[2 * np + 1][0] = v.z; b[2 * np + 1][1] = v.w;
            }
#pragma unroll
            for (int mt = 0; mt < 2; mt++)
#pragma unroll
                for (int nt = 0; nt < 8; nt++)
                    mma_f16(acc[mt][nt], a[mt], b[nt]);
        }
        __syncwarp();   // fence: A/PoPw WAR before next tap's overwrite
    }

    // ---- epilogue ----------------------------------------------------------
    float* ob = out + (size_t)n * COUT * HWSZ + hwb;
#pragma unroll
    for (int mt = 0; mt < 2; mt++) {
        const int pl = w * 32 + mt * 16 + (lane >> 2);
#pragma unroll
        for (int nt = 0; nt < 8; nt++) {
            const int co = nt * 8 + (lane & 3) * 2;
            ob[(size_t)co * HWSZ + pl]           = acc[mt][nt][0];
            ob[(size_t)(co + 1) * HWSZ + pl]     = acc[mt][nt][1];
            ob[(size_t)co * HWSZ + pl + 8]       = acc[mt][nt][2];
            ob[(size_t)(co + 1) * HWSZ + pl + 8] = acc[mt][nt][3];
        }
    }
}

// ---------------- launch ----------------------------------------------------
extern "C" void kernel_launch(void* const* d_in, const int* in_sizes, int n_in,
                              void* d_out, int out_size) {
    const float* x   = (const float*)d_in[0];
    const float* wgt = (const float*)d_in[1];
    const float* pos = (const float*)d_in[2];
    float* out = (float*)d_out;

    transpose_x<<<dim3(WD / 32, 2 * HT), dim3(32, 8)>>>(x);
    weight_frag<<<(KK2 * 4 * 4 * 32 + 255) / 256, 256>>>(wgt);
    precomp<<<HWSZ / 256, 256>>>(pos);

    cudaFuncSetAttribute(sphere_mma, cudaFuncAttributeMaxDynamicSharedMemorySize, SMEM_SZ);
    sphere_mma<<<(2 * HWSZ) / 128, 128, SMEM_SZ>>>(out);
}